// round 3
// baseline (speedup 1.0000x reference)
#include <cuda_runtime.h>
#include <cuda_fp16.h>
#include <math.h>

#define T_LEN   2048
#define TMASK   2047
#define NKEEP   1536
#define EDGE    256
#define NBC     16
#define NBAND   80
#define PHA_NB  50
#define AMP_NB  30
#define NBINS   18
#define NKTOT   640     // k = 0..639 covers all bands (max khi = 634)
#define NEV     160
#define KCH     160     // k per prefix chunk
#define NCH     4
#define PTILE   2       // p's per mi block
#define TS      6       // t-chunks in mi
#define TPB     (NKEEP / TS)   // 256 t per mi block

// ---------------- scratch (device globals; no allocations allowed) ----------
__device__ float2        g_tw[T_LEN];                  // e^{+2*pi*i*j/T}
__device__ int           g_klo[NBAND];
__device__ int           g_khi[NBAND];
__device__ int           g_evk[NEV + 1];               // sorted event k's
__device__ int           g_evslot[NEV];                // slot = 2*band + type
__device__ int           g_evstart[NCH + 1];
__device__ float2        g_Y[NBC][32 * 64];            // CT stage-A output
__device__ float2        g_Xf[NBC][NKTOT];             // DFT bins
__device__ float2        g_pref[NBC][NEV][NKEEP];      // chunk-local snapshots
__device__ float2        g_ctot[NCH - 1][NBC][NKEEP];  // chunk totals 0..2
__device__ unsigned char g_pidx[NBC][PHA_NB][NKEEP];   // phase bin index
__device__ __half        g_amp[NBC][NKEEP][AMP_NB];    // amplitude fp16
__device__ float         g_part[NBC * PHA_NB * TS * NBINS * 32];

// ---------------- init: twiddles + band ranges + sorted event list ----------
__global__ void init_kernel() {
    __shared__ int s_key[NEV];
    int tid = threadIdx.x;
    int bx  = blockIdx.x;
    // twiddle slice per block (8 blocks x 256 threads = 2048)
    {
        int j = bx * 256 + tid;
        float s, c;
        sincospif((float)j * (1.0f / 1024.0f), &s, &c);
        g_tw[j] = make_float2(c, s);
    }
    if (bx != 0) return;

    if (tid < NBAND) {
        double lo_d, hi_d;
        if (tid < PHA_NB) {
            double step = 18.0 / 49.0;
            double mid  = (tid == PHA_NB - 1) ? 20.0
                        : __dadd_rn(__dmul_rn((double)tid, step), 2.0);
            lo_d = __dmul_rn(mid, 0.75);
            hi_d = __dmul_rn(mid, 1.25);
        } else {
            int i = tid - PHA_NB;
            double ae = 256.0 / 1.8 - 1.0;
            if (ae > 160.0) ae = 160.0;
            ae = (double)(int)ae;                         // 141.0
            double step = __ddiv_rn(__dsub_rn(ae, 60.0), 29.0);
            double mid  = (i == AMP_NB - 1) ? ae
                        : __dadd_rn(__dmul_rn((double)i, step), 60.0);
            lo_d = __dmul_rn(mid, 0.875);
            hi_d = __dmul_rn(mid, 1.125);
        }
        float lo = (float)lo_d, hi = (float)hi_d;
        int klo = -1, khi = -2;
        for (int k = 1; k < NKTOT; k++) {
            float f = (float)k * 0.25f;
            if (f >= lo && f <= hi) { if (klo < 0) klo = k; khi = k; }
        }
        g_klo[tid] = klo;
        g_khi[tid] = khi;
    }
    __syncthreads();
    if (tid < NEV) {
        int b = tid >> 1, type = tid & 1;
        s_key[tid] = type ? g_khi[b] : (g_klo[b] - 1);
    }
    __syncthreads();
    if (tid < NEV) {
        int key = s_key[tid];
        int rank = 0;
        for (int j = 0; j < NEV; j++)
            rank += (s_key[j] < key) || (s_key[j] == key && j < tid);
        g_evk[rank]    = key;
        g_evslot[rank] = tid;
    }
    __syncthreads();
    if (tid == 0) {
        g_evk[NEV] = 1 << 30;
        for (int c = 0; c <= NCH; c++) {
            int s = 0;
            while (s < NEV && g_evk[s] < c * KCH) s++;
            g_evstart[c] = s;
        }
    }
}

// ---------------- kernel 1a: CT stage A -- 32 x 64-pt sub-DFTs --------------
// grid (16, 4), block 256. lane = b, warp-uniform m -> broadcast twiddles.
__global__ __launch_bounds__(256) void dftA_kernel(const float* __restrict__ x) {
    __shared__ float  s_x[T_LEN];
    __shared__ float2 s_tw64[64];     // e^{-2*pi*i*j/64}
    int bc  = blockIdx.x;
    int tid = threadIdx.x;
    for (int j = tid; j < T_LEN; j += 256) s_x[j] = x[bc * T_LEN + j];
    if (tid < 64) {
        float2 w = g_tw[tid * 32];
        s_tw64[tid] = make_float2(w.x, -w.y);
    }
    __syncthreads();

    int b  = tid & 31;
    int w8 = tid >> 5;                // 0..7, uniform per warp
#pragma unroll
    for (int i = 0; i < 2; i++) {
        int m = w8 + 8 * (2 * blockIdx.y + i);   // 0..63, uniform per warp
        float ar = 0.f, ai = 0.f;
#pragma unroll 8
        for (int a = 0; a < 64; a++) {
            float  xv = s_x[(a << 5) + b];
            float2 w  = s_tw64[(m * a) & 63];
            ar = fmaf(xv, w.x, ar);
            ai = fmaf(xv, w.y, ai);
        }
        g_Y[bc][(b << 6) + m] = make_float2(ar, ai);
    }
}

// ---------------- kernel 1b: CT stage B -- 32-term combine ------------------
// grid (16, 3), block 256: one k per thread.
__global__ __launch_bounds__(256) void dftB_kernel() {
    __shared__ float2 s_Y[32 * 64];
    __shared__ float2 s_tw[T_LEN];
    int bc  = blockIdx.x;
    int tid = threadIdx.x;
    for (int j = tid; j < 32 * 64; j += 256) s_Y[j] = g_Y[bc][j];
    for (int j = tid; j < T_LEN;   j += 256) s_tw[j] = g_tw[j];
    __syncthreads();

    int k = blockIdx.y * 256 + tid;
    if (k >= NKTOT) return;
    int km = k & 63;
    float ar = 0.f, ai = 0.f;
#pragma unroll 8
    for (int b = 0; b < 32; b++) {
        float2 y = s_Y[(b << 6) + km];
        float2 w = s_tw[(k * b) & TMASK];         // conj applied in math below
        ar += y.x * w.x + y.y * w.y;
        ai += y.y * w.x - y.x * w.y;
    }
    g_Xf[bc][k] = make_float2(ar, ai);
}

// ---------------- kernel 2: chunked prefix sweep over k ---------------------
// grid (12, 16, 4), block 128; chunk z handles k in [z*160, z*160+160).
__global__ __launch_bounds__(128) void prefix_kernel() {
    __shared__ float2 s_tw[T_LEN];
    __shared__ float2 s_Xf[KCH];
    __shared__ int    s_evk[NEV + 1];
    __shared__ int    s_evslot[NEV];
    int bc  = blockIdx.y;
    int ch  = blockIdx.z;
    int k0  = ch * KCH;
    int tid = threadIdx.x;
    for (int j = tid; j < T_LEN; j += 128) s_tw[j] = g_tw[j];
    for (int j = tid; j < KCH;   j += 128) s_Xf[j] = g_Xf[bc][k0 + j];
    for (int j = tid; j < NEV;   j += 128) { s_evk[j] = g_evk[j]; s_evslot[j] = g_evslot[j]; }
    if (tid == 0) s_evk[NEV] = 1 << 30;
    __syncthreads();

    int tk = blockIdx.x * 128 + tid;
    int t  = EDGE + tk;
    float2 w = s_tw[t];
    float S1r = 0.f, S2r = 0.f, S1i = 0.f, S2i = 0.f;
    float c1r = 0.f, c2r = 0.f, c1i = 0.f, c2i = 0.f;
    float2 z0 = s_tw[(k0 * t) & TMASK];
    float zr = z0.x, zi = z0.y;
    int j    = g_evstart[ch];
    int jend = g_evstart[ch + 1];
    int nev  = (j < jend) ? s_evk[j] : (1 << 30);

#pragma unroll 16
    for (int k = k0; k < k0 + KCH; k++) {
        if ((k & 15) == 1) {
            float2 z = s_tw[(k * t) & TMASK];
            zr = z.x; zi = z.y;
        }
        float2 X = s_Xf[k - k0];
        c1r = fmaf(X.x, zr, c1r);
        c2r = fmaf(X.y, zi, c2r);
        c1i = fmaf(X.x, zi, c1i);
        c2i = fmaf(X.y, zr, c2i);
        while (k == nev) {
            int slot = s_evslot[j];
            float vr = (S1r + c1r) - (S2r + c2r);
            float vi = (S1i + c1i) + (S2i + c2i);
            g_pref[bc][slot][tk] = make_float2(vr, vi);
            j++;
            nev = (j < jend) ? s_evk[j] : (1 << 30);
        }
        if ((k & 15) == 15) {
            S1r += c1r; S2r += c2r; S1i += c1i; S2i += c2i;
            c1r = 0.f; c2r = 0.f; c1i = 0.f; c2i = 0.f;
        }
        float nzr = zr * w.x - zi * w.y;
        float nzi = zr * w.y + zi * w.x;
        zr = nzr; zi = nzi;
    }
    if (ch < NCH - 1)
        g_ctot[ch][bc][tk] = make_float2(S1r - S2r, S1i + S2i);
}

// ---------------- kernel 2b: band tail -- snapshots + chunk-prefix ----------
// grid (12, 16), block 128.
__global__ __launch_bounds__(128) void tail_kernel() {
    __shared__ int s_klo[NBAND], s_khi[NBAND];
    int bc  = blockIdx.y;
    int tid = threadIdx.x;
    if (tid < NBAND) { s_klo[tid] = g_klo[tid]; s_khi[tid] = g_khi[tid]; }
    __syncthreads();

    int tk = blockIdx.x * 128 + tid;
    float2 T0 = g_ctot[0][bc][tk];
    float2 T1 = g_ctot[1][bc][tk];
    float2 T2 = g_ctot[2][bc][tk];
    float2 cum1 = T0;
    float2 cum2 = make_float2(cum1.x + T1.x, cum1.y + T1.y);
    float2 cum3 = make_float2(cum2.x + T2.x, cum2.y + T2.y);

    const float PIF    = 3.14159274101257324f;
    const float WIDTHF = (float)(2.0 * M_PI / (double)NBINS);
    for (int b = 0; b < NBAND; b++) {
        int ka = s_klo[b] - 1;
        int kb = s_khi[b];
        int ca = ka / KCH, cb = kb / KCH;
        float2 pa = g_pref[bc][2 * b][tk];
        float2 pb = g_pref[bc][2 * b + 1][tk];
        float2 aa = (ca == 1) ? cum1 : (ca == 2) ? cum2 : (ca == 3) ? cum3 : make_float2(0.f, 0.f);
        float2 ab = (cb == 1) ? cum1 : (cb == 2) ? cum2 : (cb == 3) ? cum3 : make_float2(0.f, 0.f);
        float re = (pb.x + ab.x) - (pa.x + aa.x);
        float im = (pb.y + ab.y) - (pa.y + aa.y);
        if (b < PHA_NB) {
            float ang = atan2f(im, re);
            float q   = __fdiv_rn(ang + PIF, WIDTHF);
            int   idx = (int)floorf(q);
            idx = max(0, min(idx, NBINS - 1));
            g_pidx[bc][b][tk] = (unsigned char)idx;
        } else {
            g_amp[bc][tk][b - PHA_NB] = __float2half_rn(sqrtf(re * re + im * im));
        }
    }
}

// ---------------- kernel 3a: partial binned sums -----------------------------
// grid (25, 16, 6), block 128 (4 warps). Run-length flush (bin is warp-uniform)
// cuts shared RMW ~2.6x. lane = amp channel (0..29), lane 30 = count.
__global__ __launch_bounds__(128) void mi_part_kernel() {
    __shared__ unsigned int s_idxw[PTILE][TPB / 4];
    __shared__ float s_acc[PTILE][4][NBINS][32];          // 18.4 KB
    int bc   = blockIdx.y;
    int p0   = blockIdx.x * PTILE;
    int zch  = blockIdx.z;
    int tid  = threadIdx.x;
    int w    = tid >> 5;
    int lane = tid & 31;
    int tbase = zch * TPB;

    for (int pp = 0; pp < PTILE; pp++) {
        const unsigned int* src =
            (const unsigned int*)&g_pidx[bc][p0 + pp][tbase];
        for (int j = tid; j < TPB / 4; j += 128) s_idxw[pp][j] = src[j];
    }
    for (int j = tid; j < PTILE * 4 * NBINS * 32; j += 128)
        ((float*)s_acc)[j] = 0.f;
    __syncthreads();

    const __half* amp = &g_amp[bc][0][0];
    int  t0    = w * (TPB / 4);          // 64 local t per warp
    bool isamp = lane < AMP_NB;
    float vconst = (lane == AMP_NB) ? 1.0f : 0.0f;

    int   kprev0 = -1, kprev1 = -1;
    float run0 = 0.f, run1 = 0.f;
    for (int c = 0; c < (TPB / 4) / 4; c++) {
        int tl = t0 + c * 4;
        int tg = tbase + tl;
        float v[4];
#pragma unroll
        for (int i = 0; i < 4; i++)
            v[i] = isamp ? __half2float(amp[(tg + i) * AMP_NB + lane]) : vconst;
        unsigned int w0 = s_idxw[0][tl >> 2];
        unsigned int w1 = s_idxw[1][tl >> 2];
#pragma unroll
        for (int i = 0; i < 4; i++) {
            int b0 = (w0 >> (8 * i)) & 255;
            int b1 = (w1 >> (8 * i)) & 255;
            if (b0 != kprev0) {                       // warp-uniform branch
                if (kprev0 >= 0) s_acc[0][w][kprev0][lane] += run0;
                kprev0 = b0; run0 = v[i];
            } else run0 += v[i];
            if (b1 != kprev1) {
                if (kprev1 >= 0) s_acc[1][w][kprev1][lane] += run1;
                kprev1 = b1; run1 = v[i];
            } else run1 += v[i];
        }
    }
    if (kprev0 >= 0) s_acc[0][w][kprev0][lane] += run0;
    if (kprev1 >= 0) s_acc[1][w][kprev1][lane] += run1;
    __syncthreads();

    // merge 4 warps, write partials
    for (int j = tid; j < NBINS * 32; j += 128) {
        int k  = j >> 5;
        int ch = j & 31;
#pragma unroll
        for (int pp = 0; pp < PTILE; pp++) {
            float s = s_acc[pp][0][k][ch] + s_acc[pp][1][k][ch]
                    + s_acc[pp][2][k][ch] + s_acc[pp][3][k][ch];
            g_part[(((bc * PHA_NB + p0 + pp) * TS + zch) * NBINS + k) * 32 + ch] = s;
        }
    }
}

// ---------------- kernel 3b: reduce partials + MI ----------------------------
// grid (50, 16), block 32. lane = channel.
__global__ __launch_bounds__(32) void mi_reduce_kernel(float* __restrict__ out) {
    int bc   = blockIdx.y;
    int p    = blockIdx.x;
    int lane = threadIdx.x;

    float means[NBINS];
    float tot = 0.f;
#pragma unroll
    for (int k = 0; k < NBINS; k++) {
        float s = 0.f;
#pragma unroll
        for (int z = 0; z < TS; z++)
            s += g_part[(((bc * PHA_NB + p) * TS + z) * NBINS + k) * 32 + lane];
        float cnt = __shfl_sync(0xffffffffu, s, AMP_NB);
        float m   = __fdiv_rn(s, fmaxf(cnt, 1e-9f));
        means[k]  = m;
        tot      += m;
    }
    float denom = fmaxf(tot, 1e-9f);
    float acc = 0.f;
#pragma unroll
    for (int k = 0; k < NBINS; k++) {
        float pr = __fdiv_rn(means[k], denom);
        acc += pr * logf(pr + 1e-9f);
    }
    const float LOG_NB = 2.8903717578961645f;   // log(18)
    if (lane < AMP_NB)
        out[(bc * PHA_NB + p) * AMP_NB + lane] = (LOG_NB + acc) / LOG_NB;
}

// ---------------- launch -----------------------------------------------------
extern "C" void kernel_launch(void* const* d_in, const int* in_sizes, int n_in,
                              void* d_out, int out_size) {
    const float* x = (const float*)d_in[0];
    float* out = (float*)d_out;

    init_kernel<<<8, 256>>>();
    dftA_kernel<<<dim3(NBC, 4), 256>>>(x);
    dftB_kernel<<<dim3(NBC, 3), 256>>>();
    prefix_kernel<<<dim3(NKEEP / 128, NBC, NCH), 128>>>();
    tail_kernel<<<dim3(NKEEP / 128, NBC), 128>>>();
    mi_part_kernel<<<dim3(PHA_NB / PTILE, NBC, TS), 128>>>();
    mi_reduce_kernel<<<dim3(PHA_NB, NBC), 32>>>(out);
}

// round 4
// speedup vs baseline: 1.5718x; 1.5718x over previous
#include <cuda_runtime.h>
#include <cuda_fp16.h>
#include <math.h>

#define T_LEN   2048
#define TMASK   2047
#define NKEEP   1536
#define EDGE    256
#define NBC     16
#define NBAND   80
#define PHA_NB  50
#define AMP_NB  30
#define NBINS   18
#define NKTOT   640     // k = 1..634 used; sweep 0..639
#define NEV     160
#define KCH     80      // k per prefix chunk
#define NCH     8
#define PTILE   2       // p's per mi block
#define TS      6       // t-chunks in mi
#define TPB     (NKEEP / TS)   // 256 t per mi block

// ---------------- compile-time tables ---------------------------------------
struct Tables {
    int evk[NEV];
    int evslot[NEV];        // slot = 2*band + type(0=klo-1,1=khi)
    int evstart[NCH + 1];
    int cha[NBAND];         // chunk of klo-1
    int chb[NBAND];         // chunk of khi
};

constexpr Tables make_tables() {
    Tables tb{};
    int klo[NBAND] = {}, khi[NBAND] = {};
    for (int b = 0; b < NBAND; b++) {
        double lo_d = 0.0, hi_d = 0.0;
        if (b < PHA_NB) {
            double step = 18.0 / 49.0;                    // numpy linspace delta
            double mid  = (b == PHA_NB - 1) ? 20.0 : ((double)b * step + 2.0);
            lo_d = mid * 0.75; hi_d = mid * 1.25;
        } else {
            int i = b - PHA_NB;
            double step = (141.0 - 60.0) / 29.0;          // amp_end = 141
            double mid  = (i == AMP_NB - 1) ? 141.0 : ((double)i * step + 60.0);
            lo_d = mid * 0.875; hi_d = mid * 1.125;
        }
        float lo = (float)lo_d, hi = (float)hi_d;
        int kl = -1, kh = -2;
        for (int k = 1; k < NKTOT; k++) {
            float f = (float)k * 0.25f;                   // exact fp32, matches jnp
            if (f >= lo && f <= hi) { if (kl < 0) kl = k; kh = k; }
        }
        klo[b] = kl; khi[b] = kh;
        tb.cha[b] = (kl - 1) / KCH;
        tb.chb[b] = kh / KCH;
    }
    int key[NEV] = {}, slot[NEV] = {};
    for (int e = 0; e < NEV; e++) {
        int b = e >> 1, type = e & 1;
        key[e]  = type ? khi[b] : (klo[b] - 1);
        slot[e] = e;
    }
    for (int i = 1; i < NEV; i++) {                        // stable insertion sort
        int k2 = key[i], s2 = slot[i], j = i - 1;
        while (j >= 0 && key[j] > k2) { key[j+1] = key[j]; slot[j+1] = slot[j]; j--; }
        key[j+1] = k2; slot[j+1] = s2;
    }
    for (int e = 0; e < NEV; e++) { tb.evk[e] = key[e]; tb.evslot[e] = slot[e]; }
    for (int c = 0; c <= NCH; c++) {
        int s = 0;
        while (s < NEV && key[s] < c * KCH) s++;
        tb.evstart[c] = s;
    }
    return tb;
}
__constant__ Tables c_tab = make_tables();

// ---------------- scratch (device globals; no allocations allowed) ----------
__device__ float2        g_Xf[NBC][NKTOT];
__device__ float2        g_pref[NBC][NEV][NKEEP];      // chunk-local snapshots
__device__ float2        g_ctot[NCH - 1][NBC][NKEEP];  // chunk totals 0..6
__device__ unsigned char g_pidx[NBC][PHA_NB][NKEEP];
__device__ __half        g_amp[NBC][NKEEP][AMP_NB];
__device__ float         g_part[NBC * PHA_NB * TS * NBINS * 32];

// ---------------- kernel 1: fused 2-stage DFT (t = 32a + b) -----------------
// grid 16, block 1024. Stage A: 64-pt sub-DFTs; stage B: 32-term combine.
__global__ __launch_bounds__(1024) void dft_kernel(const float* __restrict__ x) {
    __shared__ float  s_x[T_LEN];
    __shared__ float  s_twr[T_LEN], s_twi[T_LEN];
    __shared__ float  s_Yr[32 * 65], s_Yi[32 * 65];
    __shared__ float2 s_tw64[64];
    int bc = blockIdx.x, tid = threadIdx.x;
    for (int j = tid; j < T_LEN; j += 1024) {
        float s, c;
        sincospif((float)j * (1.0f / 1024.0f), &s, &c);
        s_twr[j] = c; s_twi[j] = s;
        s_x[j] = x[bc * T_LEN + j];
    }
    if (tid < 64) {
        float s, c;
        sincospif((float)tid * (1.0f / 32.0f), &s, &c);
        s_tw64[tid] = make_float2(c, -s);                 // e^{-2*pi*i*j/64}
    }
    __syncthreads();

    int b  = tid & 31;
    int mg = tid >> 5;
#pragma unroll
    for (int half = 0; half < 2; half++) {
        int m = mg + 32 * half;                           // warp-uniform
        float ar = 0.f, ai = 0.f;
#pragma unroll 8
        for (int a = 0; a < 64; a++) {
            float  xv = s_x[(a << 5) + b];
            float2 w  = s_tw64[(m * a) & 63];
            ar = fmaf(xv, w.x, ar);
            ai = fmaf(xv, w.y, ai);
        }
        s_Yr[b * 65 + m] = ar;
        s_Yi[b * 65 + m] = ai;
    }
    __syncthreads();

    int k = tid;
    if (k < NKTOT) {
        int km = k & 63;
        float ar = 0.f, ai = 0.f;
#pragma unroll 8
        for (int b2 = 0; b2 < 32; b2++) {
            float yr = s_Yr[b2 * 65 + km];
            float yi = s_Yi[b2 * 65 + km];
            int id = (k * b2) & TMASK;
            float wr = s_twr[id], wi = s_twi[id];         // conj applied below
            ar += yr * wr + yi * wi;
            ai += yi * wr - yr * wi;
        }
        g_Xf[bc][k] = make_float2(ar, ai);
    }
}

// ---------------- kernel 2: chunked prefix sweep over k (no smem table) -----
// grid (12, 16, 8), block 128; chunk z handles 80 k's. Rotators resynced from
// sincospif every 16 k; chunk-16 two-level accumulation bounds fp error.
__global__ __launch_bounds__(128) void prefix_kernel() {
    __shared__ float2 s_Xf[KCH];
    int bc  = blockIdx.y;
    int ch  = blockIdx.z;
    int k0  = ch * KCH;
    int tid = threadIdx.x;
    for (int j = tid; j < KCH; j += 128) s_Xf[j] = g_Xf[bc][k0 + j];
    __syncthreads();

    int tk = blockIdx.x * 128 + tid;
    int t  = EDGE + tk;
    float wr, wi;
    sincospif((float)t * (1.0f / 1024.0f), &wi, &wr);     // step e^{i*2*pi*t/2048}
    float S1r = 0.f, S2r = 0.f, S1i = 0.f, S2i = 0.f;
    int j    = c_tab.evstart[ch];
    int jend = c_tab.evstart[ch + 1];
    int nev  = (j < jend) ? c_tab.evk[j] : (1 << 30);

#pragma unroll
    for (int g = 0; g < KCH / 16; g++) {
        int kg = k0 + g * 16;
        float zr, zi;
        {
            int m = (kg * t) & TMASK;
            sincospif((float)m * (1.0f / 1024.0f), &zi, &zr);
        }
        float c1r = 0.f, c2r = 0.f, c1i = 0.f, c2i = 0.f;
#pragma unroll
        for (int kk = 0; kk < 16; kk++) {
            int k = kg + kk;
            float2 X = s_Xf[k - k0];
            c1r = fmaf(X.x, zr, c1r);
            c2r = fmaf(X.y, zi, c2r);
            c1i = fmaf(X.x, zi, c1i);
            c2i = fmaf(X.y, zr, c2i);
            if (k == nev) {
                do {
                    g_pref[bc][c_tab.evslot[j]][tk] =
                        make_float2((S1r + c1r) - (S2r + c2r),
                                    (S1i + c1i) + (S2i + c2i));
                    j++;
                    nev = (j < jend) ? c_tab.evk[j] : (1 << 30);
                } while (k == nev);
            }
            float nzr = fmaf(zr, wr, -(zi * wi));
            float nzi = fmaf(zr, wi,  (zi * wr));
            zr = nzr; zi = nzi;
        }
        S1r += c1r; S2r += c2r; S1i += c1i; S2i += c2i;
    }
    if (ch < NCH - 1)
        g_ctot[ch][bc][tk] = make_float2(S1r - S2r, S1i + S2i);
}

// ---------------- kernel 3: band tail -- snapshots + chunk-prefix -----------
// grid (12, 16, 5), block 128; band group z covers 16 bands.
__global__ __launch_bounds__(128) void tail_kernel() {
    __shared__ float s_cumr[NCH][129], s_cumi[NCH][129];
    __shared__ float s_stage[128][17];                    // amp staging (fp32)
    int bc  = blockIdx.y;
    int bg  = blockIdx.z;
    int tid = threadIdx.x;
    int tk  = blockIdx.x * 128 + tid;

    float cr = 0.f, ci = 0.f;
    s_cumr[0][tid] = 0.f; s_cumi[0][tid] = 0.f;
#pragma unroll
    for (int ch = 1; ch < NCH; ch++) {
        float2 T = g_ctot[ch - 1][bc][tk];
        cr += T.x; ci += T.y;
        s_cumr[ch][tid] = cr; s_cumi[ch][tid] = ci;
    }
    __syncthreads();

    const float PIF    = 3.14159274101257324f;
    const float WIDTHF = (float)(2.0 * M_PI / (double)NBINS);
    int abase = (bg == 3) ? 0 : 14;                       // amp col base in stage
#pragma unroll
    for (int bb = 0; bb < 16; bb++) {
        int b = bg * 16 + bb;
        float2 pa = g_pref[bc][2 * b][tk];
        float2 pb = g_pref[bc][2 * b + 1][tk];
        int ca = c_tab.cha[b], cb = c_tab.chb[b];         // warp-uniform
        float re = (pb.x + s_cumr[cb][tid]) - (pa.x + s_cumr[ca][tid]);
        float im = (pb.y + s_cumi[cb][tid]) - (pa.y + s_cumi[ca][tid]);
        if (b < PHA_NB) {
            float ang = atan2f(im, re);
            float q   = __fdiv_rn(ang + PIF, WIDTHF);
            int   idx = (int)floorf(q);
            idx = max(0, min(idx, NBINS - 1));
            g_pidx[bc][b][tk] = (unsigned char)idx;
        } else {
            s_stage[tid][b - PHA_NB - abase] = sqrtf(re * re + im * im);
        }
    }
    __syncthreads();

    if (bg >= 3) {
        int ncol = (bg == 3) ? 14 : 16;
        unsigned int* dst = (unsigned int*)&g_amp[bc][tk][abase];
#pragma unroll
        for (int c = 0; c < 8; c++) {
            if (c < ncol / 2) {
                __half2 h2 = __floats2half2_rn(s_stage[tid][2 * c],
                                               s_stage[tid][2 * c + 1]);
                dst[c] = *(unsigned int*)&h2;
            }
        }
    }
}

// ---------------- kernel 4: partial binned sums ------------------------------
// grid (25, 16, 6), block 128. Run-length flush (bin warp-uniform), lane=channel.
__global__ __launch_bounds__(128) void mi_part_kernel() {
    __shared__ unsigned int s_idxw[PTILE][TPB / 4];
    __shared__ float s_acc[PTILE][4][NBINS][32];          // 18.4 KB
    int bc   = blockIdx.y;
    int p0   = blockIdx.x * PTILE;
    int zch  = blockIdx.z;
    int tid  = threadIdx.x;
    int w    = tid >> 5;
    int lane = tid & 31;
    int tbase = zch * TPB;

    for (int pp = 0; pp < PTILE; pp++) {
        const unsigned int* src =
            (const unsigned int*)&g_pidx[bc][p0 + pp][tbase];
        for (int j = tid; j < TPB / 4; j += 128) s_idxw[pp][j] = src[j];
    }
    for (int j = tid; j < PTILE * 4 * NBINS * 32; j += 128)
        ((float*)s_acc)[j] = 0.f;
    __syncthreads();

    const __half* amp = &g_amp[bc][0][0];
    int  t0    = w * (TPB / 4);
    bool isamp = lane < AMP_NB;
    float vconst = (lane == AMP_NB) ? 1.0f : 0.0f;

    int   kprev0 = -1, kprev1 = -1;
    float run0 = 0.f, run1 = 0.f;
    for (int c = 0; c < (TPB / 4) / 4; c++) {
        int tl = t0 + c * 4;
        int tg = tbase + tl;
        float v[4];
#pragma unroll
        for (int i = 0; i < 4; i++)
            v[i] = isamp ? __half2float(amp[(tg + i) * AMP_NB + lane]) : vconst;
        unsigned int w0 = s_idxw[0][tl >> 2];
        unsigned int w1 = s_idxw[1][tl >> 2];
#pragma unroll
        for (int i = 0; i < 4; i++) {
            int b0 = (w0 >> (8 * i)) & 255;
            int b1 = (w1 >> (8 * i)) & 255;
            if (b0 != kprev0) {
                if (kprev0 >= 0) s_acc[0][w][kprev0][lane] += run0;
                kprev0 = b0; run0 = v[i];
            } else run0 += v[i];
            if (b1 != kprev1) {
                if (kprev1 >= 0) s_acc[1][w][kprev1][lane] += run1;
                kprev1 = b1; run1 = v[i];
            } else run1 += v[i];
        }
    }
    if (kprev0 >= 0) s_acc[0][w][kprev0][lane] += run0;
    if (kprev1 >= 0) s_acc[1][w][kprev1][lane] += run1;
    __syncthreads();

    for (int j = tid; j < NBINS * 32; j += 128) {
        int k  = j >> 5;
        int ch = j & 31;
#pragma unroll
        for (int pp = 0; pp < PTILE; pp++) {
            float s = s_acc[pp][0][k][ch] + s_acc[pp][1][k][ch]
                    + s_acc[pp][2][k][ch] + s_acc[pp][3][k][ch];
            g_part[(((bc * PHA_NB + p0 + pp) * TS + zch) * NBINS + k) * 32 + ch] = s;
        }
    }
}

// ---------------- kernel 5: reduce partials + MI ------------------------------
__global__ __launch_bounds__(32) void mi_reduce_kernel(float* __restrict__ out) {
    int bc   = blockIdx.y;
    int p    = blockIdx.x;
    int lane = threadIdx.x;

    float means[NBINS];
    float tot = 0.f;
#pragma unroll
    for (int k = 0; k < NBINS; k++) {
        float s = 0.f;
#pragma unroll
        for (int z = 0; z < TS; z++)
            s += g_part[(((bc * PHA_NB + p) * TS + z) * NBINS + k) * 32 + lane];
        float cnt = __shfl_sync(0xffffffffu, s, AMP_NB);
        float m   = __fdiv_rn(s, fmaxf(cnt, 1e-9f));
        means[k]  = m;
        tot      += m;
    }
    float denom = fmaxf(tot, 1e-9f);
    float acc = 0.f;
#pragma unroll
    for (int k = 0; k < NBINS; k++) {
        float pr = __fdiv_rn(means[k], denom);
        acc += pr * logf(pr + 1e-9f);
    }
    const float LOG_NB = 2.8903717578961645f;   // log(18)
    if (lane < AMP_NB)
        out[(bc * PHA_NB + p) * AMP_NB + lane] = (LOG_NB + acc) / LOG_NB;
}

// ---------------- launch -----------------------------------------------------
extern "C" void kernel_launch(void* const* d_in, const int* in_sizes, int n_in,
                              void* d_out, int out_size) {
    const float* x = (const float*)d_in[0];
    float* out = (float*)d_out;

    dft_kernel<<<NBC, 1024>>>(x);
    prefix_kernel<<<dim3(NKEEP / 128, NBC, NCH), 128>>>();
    tail_kernel<<<dim3(NKEEP / 128, NBC, 5), 128>>>();
    mi_part_kernel<<<dim3(PHA_NB / PTILE, NBC, TS), 128>>>();
    mi_reduce_kernel<<<dim3(PHA_NB, NBC), 32>>>(out);
}